// round 14
// baseline (speedup 1.0000x reference)
#include <cuda_runtime.h>
#include <cuda_fp16.h>

#define NN 100000
#define EE 1600000
#define CAP 64                         // bucket capacity; P(deg>=64) ~ 2e-18
#define NEG_SLOPE 0.2f

// ---------------- device scratch (no allocations allowed) ----------------
__device__ __half g_xh[(size_t)NN * 128];     // fp16 x_proj, 25.6 MB (L2-resident)
__device__ float  g_al[NN * 4];
__device__ float  g_ar[NN * 4];
__device__ int    g_deg[NN];                  // zero at load; agg_k re-zeros
__device__ int    g_bucket[(size_t)NN * CAP]; // 25.6 MB

// ---------------- FP16 GEMM (m16n8k16), software-pipelined staging ----------
__device__ __forceinline__ void ldg_chunk(float4* pre, const float* __restrict__ x,
                                          const float* __restrict__ W,
                                          int bm0, int kb, int tid) {
#pragma unroll
    for (int rep = 0; rep < 12; rep++) {
        int f = tid + rep * 256;
        if (f < 2048) {                       // X tile (256 x 32)
            int m = f >> 3, q = f & 7;
            float4 v = make_float4(0.f, 0.f, 0.f, 0.f);
            if (bm0 + m < NN)
                v = *(const float4*)(x + (size_t)(bm0 + m) * 128 + kb + 4 * q);
            pre[rep] = v;
        } else {                              // W tile (128 x 32)
            int f2 = f - 2048;
            int m = f2 >> 3, q = f2 & 7;
            pre[rep] = *(const float4*)(W + (size_t)m * 128 + kb + 4 * q);
        }
    }
}

__device__ __forceinline__ void sts_chunk(const float4* pre, __half (*Xs)[40],
                                          __half (*Ws)[40], int tid) {
#pragma unroll
    for (int rep = 0; rep < 12; rep++) {
        int f = tid + rep * 256;
        float4 v = pre[rep];
        __half2 h0 = __floats2half2_rn(v.x, v.y);
        __half2 h1 = __floats2half2_rn(v.z, v.w);
        uint2 u = make_uint2(*(unsigned*)&h0, *(unsigned*)&h1);
        if (f < 2048) {
            int m = f >> 3, q = f & 7;
            *(uint2*)&Xs[m][4 * q] = u;
        } else {
            int f2 = f - 2048;
            int m = f2 >> 3, q = f2 & 7;
            *(uint2*)&Ws[m][4 * q] = u;
        }
    }
}

__global__ __launch_bounds__(256) void gemm_f16_k(const float* __restrict__ x,
                                                  const float* __restrict__ W,
                                                  const float* __restrict__ attl,
                                                  const float* __restrict__ attr) {
    __shared__ __align__(16) __half Xs[256][40];
    __shared__ __align__(16) __half Ws[128][40];
    const int tid  = threadIdx.x;
    const int bm0  = blockIdx.x * 256;
    const int warp = tid >> 5;
    const int lane = tid & 31;
    const int g    = lane >> 2;
    const int tg   = lane & 3;
    const int wm0  = warp * 32;

    float acc[2][16][4];
#pragma unroll
    for (int t = 0; t < 2; t++)
#pragma unroll
        for (int nt = 0; nt < 16; nt++)
#pragma unroll
            for (int q = 0; q < 4; q++) acc[t][nt][q] = 0.f;

    float4 pre[12];
    ldg_chunk(pre, x, W, bm0, 0, tid);
    sts_chunk(pre, Xs, Ws, tid);
    __syncthreads();

#pragma unroll
    for (int kbi = 0; kbi < 4; kbi++) {
        if (kbi < 3)
            ldg_chunk(pre, x, W, bm0, (kbi + 1) * 32, tid);   // covered by MMA

#pragma unroll
        for (int ks = 0; ks < 2; ks++) {
            int k0 = ks * 16;
            unsigned a[2][4];
#pragma unroll
            for (int t = 0; t < 2; t++) {
                a[t][0] = *(const unsigned*)&Xs[wm0 + t * 16 + g][k0 + tg * 2];
                a[t][1] = *(const unsigned*)&Xs[wm0 + t * 16 + g + 8][k0 + tg * 2];
                a[t][2] = *(const unsigned*)&Xs[wm0 + t * 16 + g][k0 + tg * 2 + 8];
                a[t][3] = *(const unsigned*)&Xs[wm0 + t * 16 + g + 8][k0 + tg * 2 + 8];
            }
#pragma unroll
            for (int nt = 0; nt < 16; nt++) {
                unsigned b0 = *(const unsigned*)&Ws[nt * 8 + g][k0 + tg * 2];
                unsigned b1 = *(const unsigned*)&Ws[nt * 8 + g][k0 + tg * 2 + 8];
#pragma unroll
                for (int t = 0; t < 2; t++) {
                    asm volatile(
                        "mma.sync.aligned.m16n8k16.row.col.f32.f16.f16.f32 "
                        "{%0,%1,%2,%3}, {%4,%5,%6,%7}, {%8,%9}, {%0,%1,%2,%3};"
                        : "+f"(acc[t][nt][0]), "+f"(acc[t][nt][1]),
                          "+f"(acc[t][nt][2]), "+f"(acc[t][nt][3])
                        : "r"(a[t][0]), "r"(a[t][1]), "r"(a[t][2]), "r"(a[t][3]),
                          "r"(b0), "r"(b1));
                }
            }
        }

        if (kbi < 3) {
            __syncthreads();
            sts_chunk(pre, Xs, Ws, tid);
            __syncthreads();
        }
    }

    // ---- epilogue: fp16 store + alpha logits ----
    float pl[2][2][4], pr[2][2][4];
#pragma unroll
    for (int t = 0; t < 2; t++)
#pragma unroll
        for (int rh = 0; rh < 2; rh++)
#pragma unroll
            for (int hd = 0; hd < 4; hd++) { pl[t][rh][hd] = 0.f; pr[t][rh][hd] = 0.f; }

#pragma unroll
    for (int nt = 0; nt < 16; nt++) {
        int col = nt * 8 + tg * 2;
        int hd  = nt >> 2;
        float al0 = attl[col], al1 = attl[col + 1];
        float ar0 = attr[col], ar1 = attr[col + 1];
#pragma unroll
        for (int t = 0; t < 2; t++) {
            int r0 = bm0 + wm0 + t * 16 + g;
            int r1 = r0 + 8;
            if (r0 < NN) {
                __half2 h = __floats2half2_rn(acc[t][nt][0], acc[t][nt][1]);
                *(__half2*)(g_xh + (size_t)r0 * 128 + col) = h;
            }
            if (r1 < NN) {
                __half2 h = __floats2half2_rn(acc[t][nt][2], acc[t][nt][3]);
                *(__half2*)(g_xh + (size_t)r1 * 128 + col) = h;
            }
            pl[t][0][hd] += acc[t][nt][0] * al0 + acc[t][nt][1] * al1;
            pl[t][1][hd] += acc[t][nt][2] * al0 + acc[t][nt][3] * al1;
            pr[t][0][hd] += acc[t][nt][0] * ar0 + acc[t][nt][1] * ar1;
            pr[t][1][hd] += acc[t][nt][2] * ar0 + acc[t][nt][3] * ar1;
        }
    }
#pragma unroll
    for (int t = 0; t < 2; t++)
#pragma unroll
        for (int rh = 0; rh < 2; rh++)
#pragma unroll
            for (int hd = 0; hd < 4; hd++) {
                float vl = pl[t][rh][hd], vr = pr[t][rh][hd];
                vl += __shfl_xor_sync(0xffffffffu, vl, 1);
                vl += __shfl_xor_sync(0xffffffffu, vl, 2);
                vr += __shfl_xor_sync(0xffffffffu, vr, 1);
                vr += __shfl_xor_sync(0xffffffffu, vr, 2);
                if (tg == 0) {
                    int r = bm0 + wm0 + t * 16 + rh * 8 + g;
                    if (r < NN) {
                        g_al[r * 4 + hd] = vl;
                        g_ar[r * 4 + hd] = vr;
                    }
                }
            }
}

// ---------------- bucket CSR: single pass, no scans -------------------------
__global__ void bscatter_k(const int* __restrict__ ei) {
    int e = blockIdx.x * blockDim.x + threadIdx.x;
    if (e < EE) {
        int r = ei[e];
        int c = ei[EE + e];
        if ((unsigned)r < NN && (unsigned)c < NN) {
            int p = atomicAdd(&g_deg[r], 1);
            if (p < CAP) g_bucket[(size_t)r * CAP + p] = c;
        }
    }
}

// ---------------- fused softmax + aggregation: uniform predicated loop ------
// Warp per node; ceil(d/8) iterations, all 8-wide (4 edges per half-warp,
// MLP=4 per lane throughout). Invalid slots clamp to edge d-1 with weight 0
// (L2-hit duplicate row; no serialized MLP-1 tail). Resets g_deg.
__global__ __launch_bounds__(256) void agg_k(const float* __restrict__ bias,
                                             float* __restrict__ out) {
    int warp = (blockIdx.x * blockDim.x + threadIdx.x) >> 5;
    int lane = threadIdx.x & 31;
    if (warp >= NN) return;
    const int half = lane >> 4;
    const int hl   = lane & 15;
    const int h    = hl >> 2;
    float aln = g_al[warp * 4 + h];
    int d = g_deg[warp];
    if (d > CAP) d = CAP;
    const int* bkt = g_bucket + (size_t)warp * CAP;
    float acc[8];
#pragma unroll
    for (int i = 0; i < 8; i++) acc[i] = 0.f;
    float den = 0.f;

    for (int j = 0; j < d; j += 8) {
        int m0 = j + half * 4;
        int dm1 = d - 1;
        int i0 = m0     < d ? m0     : dm1;
        int i1 = m0 + 1 < d ? m0 + 1 : dm1;
        int i2 = m0 + 2 < d ? m0 + 2 : dm1;
        int i3 = m0 + 3 < d ? m0 + 3 : dm1;
        int c0 = bkt[i0];
        int c1 = bkt[i1];
        int c2 = bkt[i2];
        int c3 = bkt[i3];
        float a0 = g_ar[c0 * 4 + h];
        float a1 = g_ar[c1 * 4 + h];
        float a2 = g_ar[c2 * 4 + h];
        float a3 = g_ar[c3 * 4 + h];
        uint4 v0 = *(const uint4*)(g_xh + (size_t)c0 * 128 + hl * 8);
        uint4 v1 = *(const uint4*)(g_xh + (size_t)c1 * 128 + hl * 8);
        uint4 v2 = *(const uint4*)(g_xh + (size_t)c2 * 128 + hl * 8);
        uint4 v3 = *(const uint4*)(g_xh + (size_t)c3 * 128 + hl * 8);
        a0 += aln; a0 = (a0 >= 0.f) ? a0 : NEG_SLOPE * a0;
        a1 += aln; a1 = (a1 >= 0.f) ? a1 : NEG_SLOPE * a1;
        a2 += aln; a2 = (a2 >= 0.f) ? a2 : NEG_SLOPE * a2;
        a3 += aln; a3 = (a3 >= 0.f) ? a3 : NEG_SLOPE * a3;
        float w0 = (m0     < d) ? __expf(a0) : 0.f;
        float w1 = (m0 + 1 < d) ? __expf(a1) : 0.f;
        float w2 = (m0 + 2 < d) ? __expf(a2) : 0.f;
        float w3 = (m0 + 3 < d) ? __expf(a3) : 0.f;
        den += (w0 + w1) + (w2 + w3);
        float2 p;
        p = __half22float2(*(__half2*)&v0.x); acc[0] += w0 * p.x; acc[1] += w0 * p.y;
        p = __half22float2(*(__half2*)&v0.y); acc[2] += w0 * p.x; acc[3] += w0 * p.y;
        p = __half22float2(*(__half2*)&v0.z); acc[4] += w0 * p.x; acc[5] += w0 * p.y;
        p = __half22float2(*(__half2*)&v0.w); acc[6] += w0 * p.x; acc[7] += w0 * p.y;
        p = __half22float2(*(__half2*)&v1.x); acc[0] += w1 * p.x; acc[1] += w1 * p.y;
        p = __half22float2(*(__half2*)&v1.y); acc[2] += w1 * p.x; acc[3] += w1 * p.y;
        p = __half22float2(*(__half2*)&v1.z); acc[4] += w1 * p.x; acc[5] += w1 * p.y;
        p = __half22float2(*(__half2*)&v1.w); acc[6] += w1 * p.x; acc[7] += w1 * p.y;
        p = __half22float2(*(__half2*)&v2.x); acc[0] += w2 * p.x; acc[1] += w2 * p.y;
        p = __half22float2(*(__half2*)&v2.y); acc[2] += w2 * p.x; acc[3] += w2 * p.y;
        p = __half22float2(*(__half2*)&v2.z); acc[4] += w2 * p.x; acc[5] += w2 * p.y;
        p = __half22float2(*(__half2*)&v2.w); acc[6] += w2 * p.x; acc[7] += w2 * p.y;
        p = __half22float2(*(__half2*)&v3.x); acc[0] += w3 * p.x; acc[1] += w3 * p.y;
        p = __half22float2(*(__half2*)&v3.y); acc[2] += w3 * p.x; acc[3] += w3 * p.y;
        p = __half22float2(*(__half2*)&v3.z); acc[4] += w3 * p.x; acc[5] += w3 * p.y;
        p = __half22float2(*(__half2*)&v3.w); acc[6] += w3 * p.x; acc[7] += w3 * p.y;
    }

    den += __shfl_xor_sync(0xffffffffu, den, 16);
#pragma unroll
    for (int i = 0; i < 8; i++)
        acc[i] += __shfl_xor_sync(0xffffffffu, acc[i], 16);

    if (lane == 0) g_deg[warp] = 0;     // reset for next call (deterministic)

    if (half == 0) {
        float inv = 1.f / (den + 1e-16f);
        float4 b0 = *(const float4*)(bias + hl * 8);
        float4 b1 = *(const float4*)(bias + hl * 8 + 4);
        float* dst = out + (size_t)warp * 128 + hl * 8;
        *(float4*)(dst)     = make_float4(acc[0] * inv + b0.x, acc[1] * inv + b0.y,
                                          acc[2] * inv + b0.z, acc[3] * inv + b0.w);
        *(float4*)(dst + 4) = make_float4(acc[4] * inv + b1.x, acc[5] * inv + b1.y,
                                          acc[6] * inv + b1.z, acc[7] * inv + b1.w);
    }
}

// ---------------- launch: fork-join overlap of GEMM and bucket scatter ------
static cudaStream_t g_sB = nullptr;
static cudaEvent_t  g_evF = nullptr, g_evJ = nullptr;

extern "C" void kernel_launch(void* const* d_in, const int* in_sizes, int n_in,
                              void* d_out, int out_size) {
    const float* x    = (const float*)d_in[0];
    const int*   ei   = (const int*)d_in[1];
    const float* W    = (const float*)d_in[2];
    const float* attl = (const float*)d_in[3];
    const float* attr = (const float*)d_in[4];
    const float* bias = (const float*)d_in[5];
    float*       out  = (float*)d_out;

    if (g_sB == nullptr) {
        cudaStreamCreateWithFlags(&g_sB, cudaStreamNonBlocking);
        cudaEventCreateWithFlags(&g_evF, cudaEventDisableTiming);
        cudaEventCreateWithFlags(&g_evJ, cudaEventDisableTiming);
    }

    // fork: bucket scatter on side stream, GEMM on main stream
    cudaEventRecord(g_evF, 0);
    cudaStreamWaitEvent(g_sB, g_evF, 0);

    bscatter_k<<<(EE + 255) / 256, 256, 0, g_sB>>>(ei);
    cudaEventRecord(g_evJ, g_sB);

    gemm_f16_k<<<(NN + 255) / 256, 256>>>(x, W, attl, attr);

    // join, then aggregate
    cudaStreamWaitEvent(0, g_evJ, 0);
    agg_k<<<(NN + 7) / 8, 256>>>(bias, out);
}

// round 16
// speedup vs baseline: 1.0013x; 1.0013x over previous
#include <cuda_runtime.h>
#include <cuda_fp16.h>

#define NN 100000
#define EE 1600000
#define CAP 64                         // bucket capacity; P(deg>=64) ~ 2e-18
#define NEG_SLOPE 0.2f

// ---------------- device scratch (no allocations allowed) ----------------
__device__ __half g_xh[(size_t)NN * 128];     // fp16 x_proj, 25.6 MB (L2-resident)
__device__ float  g_al[NN * 4];
__device__ float  g_ar[NN * 4];
__device__ int    g_deg[NN];                  // zero at load; agg_k re-zeros
__device__ int    g_bucket[(size_t)NN * CAP]; // 25.6 MB

// ---------------- FP16 GEMM (m16n8k16), software-pipelined staging ----------
__device__ __forceinline__ void ldg_chunk(float4* pre, const float* __restrict__ x,
                                          const float* __restrict__ W,
                                          int bm0, int kb, int tid) {
#pragma unroll
    for (int rep = 0; rep < 12; rep++) {
        int f = tid + rep * 256;
        if (f < 2048) {                       // X tile (256 x 32)
            int m = f >> 3, q = f & 7;
            float4 v = make_float4(0.f, 0.f, 0.f, 0.f);
            if (bm0 + m < NN)
                v = *(const float4*)(x + (size_t)(bm0 + m) * 128 + kb + 4 * q);
            pre[rep] = v;
        } else {                              // W tile (128 x 32)
            int f2 = f - 2048;
            int m = f2 >> 3, q = f2 & 7;
            pre[rep] = *(const float4*)(W + (size_t)m * 128 + kb + 4 * q);
        }
    }
}

__device__ __forceinline__ void sts_chunk(const float4* pre, __half (*Xs)[40],
                                          __half (*Ws)[40], int tid) {
#pragma unroll
    for (int rep = 0; rep < 12; rep++) {
        int f = tid + rep * 256;
        float4 v = pre[rep];
        __half2 h0 = __floats2half2_rn(v.x, v.y);
        __half2 h1 = __floats2half2_rn(v.z, v.w);
        uint2 u = make_uint2(*(unsigned*)&h0, *(unsigned*)&h1);
        if (f < 2048) {
            int m = f >> 3, q = f & 7;
            *(uint2*)&Xs[m][4 * q] = u;
        } else {
            int f2 = f - 2048;
            int m = f2 >> 3, q = f2 & 7;
            *(uint2*)&Ws[m][4 * q] = u;
        }
    }
}

__global__ __launch_bounds__(256) void gemm_f16_k(const float* __restrict__ x,
                                                  const float* __restrict__ W,
                                                  const float* __restrict__ attl,
                                                  const float* __restrict__ attr) {
    __shared__ __align__(16) __half Xs[256][40];
    __shared__ __align__(16) __half Ws[128][40];
    const int tid  = threadIdx.x;
    const int bm0  = blockIdx.x * 256;
    const int warp = tid >> 5;
    const int lane = tid & 31;
    const int g    = lane >> 2;
    const int tg   = lane & 3;
    const int wm0  = warp * 32;

    float acc[2][16][4];
#pragma unroll
    for (int t = 0; t < 2; t++)
#pragma unroll
        for (int nt = 0; nt < 16; nt++)
#pragma unroll
            for (int q = 0; q < 4; q++) acc[t][nt][q] = 0.f;

    float4 pre[12];
    ldg_chunk(pre, x, W, bm0, 0, tid);
    sts_chunk(pre, Xs, Ws, tid);
    __syncthreads();

#pragma unroll
    for (int kbi = 0; kbi < 4; kbi++) {
        if (kbi < 3)
            ldg_chunk(pre, x, W, bm0, (kbi + 1) * 32, tid);   // covered by MMA

#pragma unroll
        for (int ks = 0; ks < 2; ks++) {
            int k0 = ks * 16;
            unsigned a[2][4];
#pragma unroll
            for (int t = 0; t < 2; t++) {
                a[t][0] = *(const unsigned*)&Xs[wm0 + t * 16 + g][k0 + tg * 2];
                a[t][1] = *(const unsigned*)&Xs[wm0 + t * 16 + g + 8][k0 + tg * 2];
                a[t][2] = *(const unsigned*)&Xs[wm0 + t * 16 + g][k0 + tg * 2 + 8];
                a[t][3] = *(const unsigned*)&Xs[wm0 + t * 16 + g + 8][k0 + tg * 2 + 8];
            }
#pragma unroll
            for (int nt = 0; nt < 16; nt++) {
                unsigned b0 = *(const unsigned*)&Ws[nt * 8 + g][k0 + tg * 2];
                unsigned b1 = *(const unsigned*)&Ws[nt * 8 + g][k0 + tg * 2 + 8];
#pragma unroll
                for (int t = 0; t < 2; t++) {
                    asm volatile(
                        "mma.sync.aligned.m16n8k16.row.col.f32.f16.f16.f32 "
                        "{%0,%1,%2,%3}, {%4,%5,%6,%7}, {%8,%9}, {%0,%1,%2,%3};"
                        : "+f"(acc[t][nt][0]), "+f"(acc[t][nt][1]),
                          "+f"(acc[t][nt][2]), "+f"(acc[t][nt][3])
                        : "r"(a[t][0]), "r"(a[t][1]), "r"(a[t][2]), "r"(a[t][3]),
                          "r"(b0), "r"(b1));
                }
            }
        }

        if (kbi < 3) {
            __syncthreads();
            sts_chunk(pre, Xs, Ws, tid);
            __syncthreads();
        }
    }

    // ---- epilogue: fp16 store + alpha logits ----
    float pl[2][2][4], pr[2][2][4];
#pragma unroll
    for (int t = 0; t < 2; t++)
#pragma unroll
        for (int rh = 0; rh < 2; rh++)
#pragma unroll
            for (int hd = 0; hd < 4; hd++) { pl[t][rh][hd] = 0.f; pr[t][rh][hd] = 0.f; }

#pragma unroll
    for (int nt = 0; nt < 16; nt++) {
        int col = nt * 8 + tg * 2;
        int hd  = nt >> 2;
        float al0 = attl[col], al1 = attl[col + 1];
        float ar0 = attr[col], ar1 = attr[col + 1];
#pragma unroll
        for (int t = 0; t < 2; t++) {
            int r0 = bm0 + wm0 + t * 16 + g;
            int r1 = r0 + 8;
            if (r0 < NN) {
                __half2 h = __floats2half2_rn(acc[t][nt][0], acc[t][nt][1]);
                *(__half2*)(g_xh + (size_t)r0 * 128 + col) = h;
            }
            if (r1 < NN) {
                __half2 h = __floats2half2_rn(acc[t][nt][2], acc[t][nt][3]);
                *(__half2*)(g_xh + (size_t)r1 * 128 + col) = h;
            }
            pl[t][0][hd] += acc[t][nt][0] * al0 + acc[t][nt][1] * al1;
            pl[t][1][hd] += acc[t][nt][2] * al0 + acc[t][nt][3] * al1;
            pr[t][0][hd] += acc[t][nt][0] * ar0 + acc[t][nt][1] * ar1;
            pr[t][1][hd] += acc[t][nt][2] * ar0 + acc[t][nt][3] * ar1;
        }
    }
#pragma unroll
    for (int t = 0; t < 2; t++)
#pragma unroll
        for (int rh = 0; rh < 2; rh++)
#pragma unroll
            for (int hd = 0; hd < 4; hd++) {
                float vl = pl[t][rh][hd], vr = pr[t][rh][hd];
                vl += __shfl_xor_sync(0xffffffffu, vl, 1);
                vl += __shfl_xor_sync(0xffffffffu, vl, 2);
                vr += __shfl_xor_sync(0xffffffffu, vr, 1);
                vr += __shfl_xor_sync(0xffffffffu, vr, 2);
                if (tg == 0) {
                    int r = bm0 + wm0 + t * 16 + rh * 8 + g;
                    if (r < NN) {
                        g_al[r * 4 + hd] = vl;
                        g_ar[r * 4 + hd] = vr;
                    }
                }
            }
}

// ---------------- bucket CSR: single pass, no scans -------------------------
__global__ void bscatter_k(const int* __restrict__ ei) {
    int e = blockIdx.x * blockDim.x + threadIdx.x;
    if (e < EE) {
        int r = ei[e];
        int c = ei[EE + e];
        if ((unsigned)r < NN && (unsigned)c < NN) {
            int p = atomicAdd(&g_deg[r], 1);
            if (p < CAP) g_bucket[(size_t)r * CAP + p] = c;
        }
    }
}

// ---------------- fused softmax + aggregation -------------------------------
// Warp per node; 16-edge front loop (8/half, MLP=8) -> 8-edge loop (MLP=4)
// -> 2-edge tail. No wasted gathers (R14 lesson). Resets g_deg.
#define EDGE_STEP(vv, ww)                                                      \
    do {                                                                       \
        float2 p_;                                                             \
        p_ = __half22float2(*(__half2*)&(vv).x); acc[0] += (ww) * p_.x; acc[1] += (ww) * p_.y; \
        p_ = __half22float2(*(__half2*)&(vv).y); acc[2] += (ww) * p_.x; acc[3] += (ww) * p_.y; \
        p_ = __half22float2(*(__half2*)&(vv).z); acc[4] += (ww) * p_.x; acc[5] += (ww) * p_.y; \
        p_ = __half22float2(*(__half2*)&(vv).w); acc[6] += (ww) * p_.x; acc[7] += (ww) * p_.y; \
    } while (0)

__global__ __launch_bounds__(256) void agg_k(const float* __restrict__ bias,
                                             float* __restrict__ out) {
    int warp = (blockIdx.x * blockDim.x + threadIdx.x) >> 5;
    int lane = threadIdx.x & 31;
    if (warp >= NN) return;
    const int half = lane >> 4;
    const int hl   = lane & 15;
    const int h    = hl >> 2;
    float aln = g_al[warp * 4 + h];
    int d = g_deg[warp];
    if (d > CAP) d = CAP;
    const int* bkt = g_bucket + (size_t)warp * CAP;
    float acc[8];
#pragma unroll
    for (int i = 0; i < 8; i++) acc[i] = 0.f;
    float den = 0.f;

    int j = 0;
    // front loop: 16 edges / iteration (8 per half, MLP=8 per lane)
    for (; j + 16 <= d; j += 16) {
        int m0 = j + half * 8;
        int c[8];
#pragma unroll
        for (int q = 0; q < 8; q++) c[q] = bkt[m0 + q];
        float a[8];
#pragma unroll
        for (int q = 0; q < 8; q++) a[q] = g_ar[c[q] * 4 + h];
        uint4 v[8];
#pragma unroll
        for (int q = 0; q < 8; q++)
            v[q] = *(const uint4*)(g_xh + (size_t)c[q] * 128 + hl * 8);
        float w[8];
#pragma unroll
        for (int q = 0; q < 8; q++) {
            float t = a[q] + aln;
            t = (t >= 0.f) ? t : NEG_SLOPE * t;
            w[q] = __expf(t);
            den += w[q];
        }
#pragma unroll
        for (int q = 0; q < 8; q++) EDGE_STEP(v[q], w[q]);
    }
    // middle loop: 8 edges / iteration (4 per half, MLP=4)
    for (; j + 8 <= d; j += 8) {
        int m0 = j + half * 4;
        int c0 = bkt[m0];
        int c1 = bkt[m0 + 1];
        int c2 = bkt[m0 + 2];
        int c3 = bkt[m0 + 3];
        float a0 = g_ar[c0 * 4 + h];
        float a1 = g_ar[c1 * 4 + h];
        float a2 = g_ar[c2 * 4 + h];
        float a3 = g_ar[c3 * 4 + h];
        uint4 v0 = *(const uint4*)(g_xh + (size_t)c0 * 128 + hl * 8);
        uint4 v1 = *(const uint4*)(g_xh + (size_t)c1 * 128 + hl * 8);
        uint4 v2 = *(const uint4*)(g_xh + (size_t)c2 * 128 + hl * 8);
        uint4 v3 = *(const uint4*)(g_xh + (size_t)c3 * 128 + hl * 8);
        a0 += aln; a0 = (a0 >= 0.f) ? a0 : NEG_SLOPE * a0;
        a1 += aln; a1 = (a1 >= 0.f) ? a1 : NEG_SLOPE * a1;
        a2 += aln; a2 = (a2 >= 0.f) ? a2 : NEG_SLOPE * a2;
        a3 += aln; a3 = (a3 >= 0.f) ? a3 : NEG_SLOPE * a3;
        float w0 = __expf(a0), w1 = __expf(a1), w2 = __expf(a2), w3 = __expf(a3);
        den += (w0 + w1) + (w2 + w3);
        EDGE_STEP(v0, w0);
        EDGE_STEP(v1, w1);
        EDGE_STEP(v2, w2);
        EDGE_STEP(v3, w3);
    }
    // tail: 2 edges / iteration (1 per half), clamped
    for (; j < d; j += 2) {
        int m = j + half;
        bool valid = (m < d);
        int c = bkt[valid ? m : (d - 1)];
        float a = aln + g_ar[c * 4 + h];
        a = (a >= 0.f) ? a : NEG_SLOPE * a;
        float w = valid ? __expf(a) : 0.f;
        uint4 v = *(const uint4*)(g_xh + (size_t)c * 128 + hl * 8);
        den += w;
        EDGE_STEP(v, w);
    }

    den += __shfl_xor_sync(0xffffffffu, den, 16);
#pragma unroll
    for (int i = 0; i < 8; i++)
        acc[i] += __shfl_xor_sync(0xffffffffu, acc[i], 16);

    if (lane == 0) g_deg[warp] = 0;     // reset for next call (deterministic)

    if (half == 0) {
        float inv = 1.f / (den + 1e-16f);
        float4 b0 = *(const float4*)(bias + hl * 8);
        float4 b1 = *(const float4*)(bias + hl * 8 + 4);
        float* dst = out + (size_t)warp * 128 + hl * 8;
        *(float4*)(dst)     = make_float4(acc[0] * inv + b0.x, acc[1] * inv + b0.y,
                                          acc[2] * inv + b0.z, acc[3] * inv + b0.w);
        *(float4*)(dst + 4) = make_float4(acc[4] * inv + b1.x, acc[5] * inv + b1.y,
                                          acc[6] * inv + b1.z, acc[7] * inv + b1.w);
    }
}

// ---------------- launch: fork-join overlap of GEMM and bucket scatter ------
static cudaStream_t g_sB = nullptr;
static cudaEvent_t  g_evF = nullptr, g_evJ = nullptr;

extern "C" void kernel_launch(void* const* d_in, const int* in_sizes, int n_in,
                              void* d_out, int out_size) {
    const float* x    = (const float*)d_in[0];
    const int*   ei   = (const int*)d_in[1];
    const float* W    = (const float*)d_in[2];
    const float* attl = (const float*)d_in[3];
    const float* attr = (const float*)d_in[4];
    const float* bias = (const float*)d_in[5];
    float*       out  = (float*)d_out;

    if (g_sB == nullptr) {
        cudaStreamCreateWithFlags(&g_sB, cudaStreamNonBlocking);
        cudaEventCreateWithFlags(&g_evF, cudaEventDisableTiming);
        cudaEventCreateWithFlags(&g_evJ, cudaEventDisableTiming);
    }

    // fork: bucket scatter on side stream, GEMM on main stream
    cudaEventRecord(g_evF, 0);
    cudaStreamWaitEvent(g_sB, g_evF, 0);

    bscatter_k<<<(EE + 255) / 256, 256, 0, g_sB>>>(ei);
    cudaEventRecord(g_evJ, g_sB);

    gemm_f16_k<<<(NN + 255) / 256, 256>>>(x, W, attl, attr);

    // join, then aggregate
    cudaStreamWaitEvent(0, g_evJ, 0);
    agg_k<<<(NN + 7) / 8, 256>>>(bias, out);
}